// round 5
// baseline (speedup 1.0000x reference)
#include <cuda_runtime.h>

// ---------------------------------------------------------------------------
// SpatialCrossAttention — fp32 baseline
//   B=8, C=256, W=H=64 -> N=4096, DQK=16
//   out layout: [out1 (8*256*4096) | out2 (8*256*4096) | attention (8*4096*4096)]
// ---------------------------------------------------------------------------

#define BATCH 8
#define CH    256
#define NPIX  4096
#define DQK   16
#define TWO_C 512

// GEMM tiling
#define BM 128
#define BN 128
#define TK 16
#define PAD 4

// ---- device scratch (no allocations allowed) ----
__device__ float g_q[BATCH * DQK * NPIX];              // 2 MB
__device__ float g_k[BATCH * DQK * NPIX];              // 2 MB
__device__ float g_v[2][BATCH * CH * NPIX];            // 64 MB

// ===========================================================================
// Kernel 1: q/k projection.  q[b,d,n] = sum_c Wq[d,c]*xcat[b,c,n] + bq[d]
// grid (N/32, B), 256 threads. Each block: 32 spatial positions, all 32 outputs.
// ===========================================================================
__global__ __launch_bounds__(256) void qk_kernel(
    const float* __restrict__ x1, const float* __restrict__ x2,
    const float* __restrict__ Wq, const float* __restrict__ bq,
    const float* __restrict__ Wk, const float* __restrict__ bk)
{
    __shared__ float xs[64][33];
    __shared__ float wqs[16][64];
    __shared__ float wks[16][64];

    const int n0  = blockIdx.x * 32;
    const int b   = blockIdx.y;
    const int tid = threadIdx.x;
    const int nl  = tid & 31;
    const int dg  = tid >> 5;   // 0..7

    float aq0 = 0.f, aq1 = 0.f, ak0 = 0.f, ak1 = 0.f;

    for (int c0 = 0; c0 < TWO_C; c0 += 64) {
        // load x tile (64 channels x 32 positions), coalesced in n
        for (int r = dg; r < 64; r += 8) {
            const int c = c0 + r;
            const float* src = (c < CH) ? x1 : x2;
            xs[r][nl] = src[((size_t)b * CH + (c & (CH - 1))) * NPIX + n0 + nl];
        }
        // load weight chunks
        for (int i = tid; i < 16 * 64; i += 256) {
            const int d = i >> 6, cc = i & 63;
            wqs[d][cc] = Wq[d * TWO_C + c0 + cc];
            wks[d][cc] = Wk[d * TWO_C + c0 + cc];
        }
        __syncthreads();
        #pragma unroll
        for (int cc = 0; cc < 64; cc++) {
            const float xv = xs[cc][nl];
            aq0 = fmaf(wqs[dg    ][cc], xv, aq0);
            aq1 = fmaf(wqs[dg + 8][cc], xv, aq1);
            ak0 = fmaf(wks[dg    ][cc], xv, ak0);
            ak1 = fmaf(wks[dg + 8][cc], xv, ak1);
        }
        __syncthreads();
    }

    const size_t base = (size_t)b * DQK * NPIX + n0 + nl;
    g_q[base + (size_t)(dg    ) * NPIX] = aq0 + bq[dg];
    g_q[base + (size_t)(dg + 8) * NPIX] = aq1 + bq[dg + 8];
    g_k[base + (size_t)(dg    ) * NPIX] = ak0 + bk[dg];
    g_k[base + (size_t)(dg + 8) * NPIX] = ak1 + bk[dg + 8];
}

// ===========================================================================
// Kernel 2: v projection GEMM.  v[b,o,n] = sum_c Wv[o,c]*x[b,c,n] + bv[o]
// Double-buffered 128x128x16 SGEMM, 8x8 thread tiles.
// grid (N/BN, CH/BM, 2*B) ; z = b*2 + which
// ===========================================================================
__global__ __launch_bounds__(256, 2) void v_gemm_kernel(
    const float* __restrict__ x1, const float* __restrict__ x2,
    const float* __restrict__ Wv1, const float* __restrict__ bv1,
    const float* __restrict__ Wv2, const float* __restrict__ bv2)
{
    __shared__ float As[2][TK][BM + PAD];
    __shared__ float Bs[2][TK][BN + PAD];

    const int which = blockIdx.z & 1;
    const int b     = blockIdx.z >> 1;
    const float* __restrict__ Wv = which ? Wv2 : Wv1;
    const float* __restrict__ bv = which ? bv2 : bv1;
    const float* __restrict__ Xb = (which ? x2 : x1) + (size_t)b * CH * NPIX;
    float* __restrict__ V        = g_v[which] + (size_t)b * CH * NPIX;

    const int n0  = blockIdx.x * BN;
    const int o0  = blockIdx.y * BM;
    const int tid = threadIdx.x;
    const int tx  = tid & 15, ty = tid >> 4;

    const int ar  = tid >> 2;          // 0..63  (A row)
    const int ak  = (tid & 3) << 2;    // 0,4,8,12 (A k-col, float4)
    const int bkr = tid >> 5;          // 0..7   (B k-row)
    const int bj  = (tid & 31) << 2;   // 0..124 (B n-col, float4)

    float acc[8][8];
    #pragma unroll
    for (int r = 0; r < 8; r++)
        #pragma unroll
        for (int s = 0; s < 8; s++) acc[r][s] = 0.f;

    const int KT = CH / TK;  // 16
    float4 a0n, a1n, b0n, b1n;

    // prologue: tile 0 -> buffer 0
    {
        const float* ap = Wv + (o0 + ar) * CH + ak;
        a0n = *(const float4*)ap;
        a1n = *(const float4*)(ap + 64 * CH);
        const float* bp = Xb + (size_t)bkr * NPIX + n0 + bj;
        b0n = *(const float4*)bp;
        b1n = *(const float4*)(bp + (size_t)8 * NPIX);
        As[0][ak + 0][ar] = a0n.x; As[0][ak + 1][ar] = a0n.y;
        As[0][ak + 2][ar] = a0n.z; As[0][ak + 3][ar] = a0n.w;
        As[0][ak + 0][ar + 64] = a1n.x; As[0][ak + 1][ar + 64] = a1n.y;
        As[0][ak + 2][ar + 64] = a1n.z; As[0][ak + 3][ar + 64] = a1n.w;
        *(float4*)&Bs[0][bkr    ][bj] = b0n;
        *(float4*)&Bs[0][bkr + 8][bj] = b1n;
    }
    __syncthreads();

    for (int kt = 0; kt < KT; kt++) {
        const int cur = kt & 1;
        const bool pf = (kt + 1 < KT);
        if (pf) {
            const int kc = (kt + 1) * TK;
            const float* ap = Wv + (o0 + ar) * CH + kc + ak;
            a0n = *(const float4*)ap;
            a1n = *(const float4*)(ap + 64 * CH);
            const float* bp = Xb + (size_t)(kc + bkr) * NPIX + n0 + bj;
            b0n = *(const float4*)bp;
            b1n = *(const float4*)(bp + (size_t)8 * NPIX);
        }
        #pragma unroll
        for (int k = 0; k < TK; k++) {
            const float4 a0 = *(const float4*)&As[cur][k][ty * 4];
            const float4 a1 = *(const float4*)&As[cur][k][64 + ty * 4];
            const float4 b0 = *(const float4*)&Bs[cur][k][tx * 4];
            const float4 b1 = *(const float4*)&Bs[cur][k][64 + tx * 4];
            const float av[8] = {a0.x, a0.y, a0.z, a0.w, a1.x, a1.y, a1.z, a1.w};
            const float bw[8] = {b0.x, b0.y, b0.z, b0.w, b1.x, b1.y, b1.z, b1.w};
            #pragma unroll
            for (int r = 0; r < 8; r++)
                #pragma unroll
                for (int s = 0; s < 8; s++)
                    acc[r][s] = fmaf(av[r], bw[s], acc[r][s]);
        }
        if (pf) {
            const int nb = cur ^ 1;
            As[nb][ak + 0][ar] = a0n.x; As[nb][ak + 1][ar] = a0n.y;
            As[nb][ak + 2][ar] = a0n.z; As[nb][ak + 3][ar] = a0n.w;
            As[nb][ak + 0][ar + 64] = a1n.x; As[nb][ak + 1][ar + 64] = a1n.y;
            As[nb][ak + 2][ar + 64] = a1n.z; As[nb][ak + 3][ar + 64] = a1n.w;
            *(float4*)&Bs[nb][bkr    ][bj] = b0n;
            *(float4*)&Bs[nb][bkr + 8][bj] = b1n;
        }
        __syncthreads();
    }

    // epilogue: + bias, store
    #pragma unroll
    for (int rg = 0; rg < 2; rg++)
        #pragma unroll
        for (int rr = 0; rr < 4; rr++) {
            const int r = rg * 4 + rr;
            const int o = o0 + rg * 64 + ty * 4 + rr;
            const float bias = __ldg(&bv[o]);
            float* dst = V + (size_t)o * NPIX + n0;
            const float4 v0 = make_float4(acc[r][0] + bias, acc[r][1] + bias,
                                          acc[r][2] + bias, acc[r][3] + bias);
            const float4 v1 = make_float4(acc[r][4] + bias, acc[r][5] + bias,
                                          acc[r][6] + bias, acc[r][7] + bias);
            *(float4*)(dst + tx * 4)      = v0;
            *(float4*)(dst + 64 + tx * 4) = v1;
        }
}

// ===========================================================================
// Kernel 3: energy + softmax -> attention (written directly to d_out region)
// grid (N/32, B), 256 threads. 32 query rows/block; warp w owns rows 4w..4w+3.
// Two passes over m (k is L2-resident, 256KB/batch): pass1 online max/sum,
// pass2 recompute energy (identical fma order) and write exp(e-max)/sum.
// ===========================================================================
__global__ __launch_bounds__(256) void attn_kernel(float* __restrict__ att)
{
    __shared__ float ks[16][256];
    __shared__ float qs[16][32];
    __shared__ float s_mx[32];
    __shared__ float s_inv[32];

    const int n0   = blockIdx.x * 32;
    const int b    = blockIdx.y;
    const int tid  = threadIdx.x;
    const int lane = tid & 31;
    const int w    = tid >> 5;
    const int rb   = w * 4;

    const float* __restrict__ qb = g_q + (size_t)b * DQK * NPIX;
    const float* __restrict__ kb = g_k + (size_t)b * DQK * NPIX;
    float* __restrict__ attb     = att + (size_t)b * NPIX * NPIX;

    // stage q tile, then hoist to registers
    for (int i = tid; i < 512; i += 256) {
        const int d = i >> 5, nl = i & 31;
        qs[d][nl] = qb[(size_t)d * NPIX + n0 + nl];
    }
    __syncthreads();
    float qr[4][16];
    #pragma unroll
    for (int rr = 0; rr < 4; rr++)
        #pragma unroll
        for (int d = 0; d < 16; d++)
            qr[rr][d] = qs[d][rb + rr];

    float mx[4], sm[4];
    #pragma unroll
    for (int rr = 0; rr < 4; rr++) { mx[rr] = -1e30f; sm[rr] = 0.f; }

    // ---- pass 1: online max / sumexp ----
    for (int m0 = 0; m0 < NPIX; m0 += 256) {
        __syncthreads();
        #pragma unroll
        for (int r = 0; r < 4; r++) {
            const int lin = tid + 256 * r;
            const int d = lin >> 6, mm4 = (lin & 63) << 2;
            *(float4*)&ks[d][mm4] = *(const float4*)&kb[(size_t)d * NPIX + m0 + mm4];
        }
        __syncthreads();
        #pragma unroll
        for (int it = 0; it < 8; it++) {
            const int mm = lane + it * 32;
            float e0 = 0.f, e1 = 0.f, e2 = 0.f, e3 = 0.f;
            #pragma unroll
            for (int d = 0; d < 16; d++) {
                const float kv = ks[d][mm];
                e0 = fmaf(qr[0][d], kv, e0);
                e1 = fmaf(qr[1][d], kv, e1);
                e2 = fmaf(qr[2][d], kv, e2);
                e3 = fmaf(qr[3][d], kv, e3);
            }
            { const float dd = e0 - mx[0]; if (dd > 0.f) { sm[0] = sm[0] * __expf(-dd) + 1.f; mx[0] = e0; } else sm[0] += __expf(dd); }
            { const float dd = e1 - mx[1]; if (dd > 0.f) { sm[1] = sm[1] * __expf(-dd) + 1.f; mx[1] = e1; } else sm[1] += __expf(dd); }
            { const float dd = e2 - mx[2]; if (dd > 0.f) { sm[2] = sm[2] * __expf(-dd) + 1.f; mx[2] = e2; } else sm[2] += __expf(dd); }
            { const float dd = e3 - mx[3]; if (dd > 0.f) { sm[3] = sm[3] * __expf(-dd) + 1.f; mx[3] = e3; } else sm[3] += __expf(dd); }
        }
    }

    // combine per-lane partials across the warp
    #pragma unroll
    for (int rr = 0; rr < 4; rr++) {
        float m = mx[rr], s = sm[rr];
        #pragma unroll
        for (int off = 16; off; off >>= 1) {
            const float om = __shfl_xor_sync(0xffffffffu, m, off);
            const float os = __shfl_xor_sync(0xffffffffu, s, off);
            const float nm = fmaxf(m, om);
            s = s * __expf(m - nm) + os * __expf(om - nm);
            m = nm;
        }
        if (lane == 0) { s_mx[rb + rr] = m; s_inv[rb + rr] = 1.f / s; }
    }
    __syncthreads();
    float fm[4], fi[4];
    #pragma unroll
    for (int rr = 0; rr < 4; rr++) { fm[rr] = s_mx[rb + rr]; fi[rr] = s_inv[rb + rr]; }

    // ---- pass 2: recompute energy, write normalized attention ----
    for (int m0 = 0; m0 < NPIX; m0 += 256) {
        __syncthreads();
        #pragma unroll
        for (int r = 0; r < 4; r++) {
            const int lin = tid + 256 * r;
            const int d = lin >> 6, mm4 = (lin & 63) << 2;
            *(float4*)&ks[d][mm4] = *(const float4*)&kb[(size_t)d * NPIX + m0 + mm4];
        }
        __syncthreads();
        #pragma unroll
        for (int it = 0; it < 8; it++) {
            const int mm = lane + it * 32;
            float e0 = 0.f, e1 = 0.f, e2 = 0.f, e3 = 0.f;
            #pragma unroll
            for (int d = 0; d < 16; d++) {
                const float kv = ks[d][mm];
                e0 = fmaf(qr[0][d], kv, e0);
                e1 = fmaf(qr[1][d], kv, e1);
                e2 = fmaf(qr[2][d], kv, e2);
                e3 = fmaf(qr[3][d], kv, e3);
            }
            attb[(size_t)(n0 + rb + 0) * NPIX + m0 + mm] = __expf(e0 - fm[0]) * fi[0];
            attb[(size_t)(n0 + rb + 1) * NPIX + m0 + mm] = __expf(e1 - fm[1]) * fi[1];
            attb[(size_t)(n0 + rb + 2) * NPIX + m0 + mm] = __expf(e2 - fm[2]) * fi[2];
            attb[(size_t)(n0 + rb + 3) * NPIX + m0 + mm] = __expf(e3 - fm[3]) * fi[3];
        }
    }
}

// ===========================================================================
// Kernel 4: out[b,c,n] = x[b,c,n] + sum_m v[b,c,m] * att[b,n,m]
// Same SGEMM skeleton; B tile = att rows (m-contiguous) transposed into smem.
// grid (N/BN, CH/BM, 2*B)
// ===========================================================================
__global__ __launch_bounds__(256, 2) void out_gemm_kernel(
    const float* __restrict__ x1, const float* __restrict__ x2,
    const float* __restrict__ att, float* __restrict__ out)
{
    __shared__ float As[2][TK][BM + PAD];
    __shared__ float Bs[2][TK][BN + PAD];

    const int which = blockIdx.z & 1;
    const int b     = blockIdx.z >> 1;
    const float* __restrict__ Vb = g_v[which] + (size_t)b * CH * NPIX;       // A [256][4096]
    const float* __restrict__ Ab = att + (size_t)b * NPIX * NPIX;            // att rows
    const float* __restrict__ Xb = (which ? x2 : x1) + (size_t)b * CH * NPIX;
    float* __restrict__ Ob = out + (size_t)which * BATCH * CH * NPIX + (size_t)b * CH * NPIX;

    const int n0  = blockIdx.x * BN;
    const int c0  = blockIdx.y * BM;
    const int tid = threadIdx.x;
    const int tx  = tid & 15, ty = tid >> 4;

    const int ar  = tid >> 2;          // A row (c) / B row (n)
    const int ak  = (tid & 3) << 2;    // k-offset within tile, float4

    float acc[8][8];
    #pragma unroll
    for (int r = 0; r < 8; r++)
        #pragma unroll
        for (int s = 0; s < 8; s++) acc[r][s] = 0.f;

    const int KT = NPIX / TK;  // 256
    float4 a0n, a1n, b0n, b1n;

    // prologue: tile 0
    {
        const float* ap = Vb + (size_t)(c0 + ar) * NPIX + ak;
        a0n = *(const float4*)ap;
        a1n = *(const float4*)(ap + (size_t)64 * NPIX);
        const float* bp = Ab + (size_t)(n0 + ar) * NPIX + ak;
        b0n = *(const float4*)bp;
        b1n = *(const float4*)(bp + (size_t)64 * NPIX);
        As[0][ak + 0][ar] = a0n.x; As[0][ak + 1][ar] = a0n.y;
        As[0][ak + 2][ar] = a0n.z; As[0][ak + 3][ar] = a0n.w;
        As[0][ak + 0][ar + 64] = a1n.x; As[0][ak + 1][ar + 64] = a1n.y;
        As[0][ak + 2][ar + 64] = a1n.z; As[0][ak + 3][ar + 64] = a1n.w;
        Bs[0][ak + 0][ar] = b0n.x; Bs[0][ak + 1][ar] = b0n.y;
        Bs[0][ak + 2][ar] = b0n.z; Bs[0][ak + 3][ar] = b0n.w;
        Bs[0][ak + 0][ar + 64] = b1n.x; Bs[0][ak + 1][ar + 64] = b1n.y;
        Bs[0][ak + 2][ar + 64] = b1n.z; Bs[0][ak + 3][ar + 64] = b1n.w;
    }
    __syncthreads();

    for (int kt = 0; kt < KT; kt++) {
        const int cur = kt & 1;
        const bool pf = (kt + 1 < KT);
        if (pf) {
            const int kc = (kt + 1) * TK;
            const float* ap = Vb + (size_t)(c0 + ar) * NPIX + kc + ak;
            a0n = *(const float4*)ap;
            a1n = *(const float4*)(ap + (size_t)64 * NPIX);
            const float* bp = Ab + (size_t)(n0 + ar) * NPIX + kc + ak;
            b0n = *(const float4*)bp;
            b1n = *(const float4*)(bp + (size_t)64 * NPIX);
        }
        #pragma unroll
        for (int k = 0; k < TK; k++) {
            const float4 a0 = *(const float4*)&As[cur][k][ty * 4];
            const float4 a1 = *(const float4*)&As[cur][k][64 + ty * 4];
            const float4 b0 = *(const float4*)&Bs[cur][k][tx * 4];
            const float4 b1 = *(const float4*)&Bs[cur][k][64 + tx * 4];
            const float av[8] = {a0.x, a0.y, a0.z, a0.w, a1.x, a1.y, a1.z, a1.w};
            const float bw[8] = {b0.x, b0.y, b0.z, b0.w, b1.x, b1.y, b1.z, b1.w};
            #pragma unroll
            for (int r = 0; r < 8; r++)
                #pragma unroll
                for (int s = 0; s < 8; s++)
                    acc[r][s] = fmaf(av[r], bw[s], acc[r][s]);
        }
        if (pf) {
            const int nb = cur ^ 1;
            As[nb][ak + 0][ar] = a0n.x; As[nb][ak + 1][ar] = a0n.y;
            As[nb][ak + 2][ar] = a0n.z; As[nb][ak + 3][ar] = a0n.w;
            As[nb][ak + 0][ar + 64] = a1n.x; As[nb][ak + 1][ar + 64] = a1n.y;
            As[nb][ak + 2][ar + 64] = a1n.z; As[nb][ak + 3][ar + 64] = a1n.w;
            Bs[nb][ak + 0][ar] = b0n.x; Bs[nb][ak + 1][ar] = b0n.y;
            Bs[nb][ak + 2][ar] = b0n.z; Bs[nb][ak + 3][ar] = b0n.w;
            Bs[nb][ak + 0][ar + 64] = b1n.x; Bs[nb][ak + 1][ar + 64] = b1n.y;
            Bs[nb][ak + 2][ar + 64] = b1n.z; Bs[nb][ak + 3][ar + 64] = b1n.w;
        }
        __syncthreads();
    }

    // epilogue: + residual x, store
    #pragma unroll
    for (int rg = 0; rg < 2; rg++)
        #pragma unroll
        for (int rr = 0; rr < 4; rr++) {
            const int r = rg * 4 + rr;
            const int c = c0 + rg * 64 + ty * 4 + rr;
            const size_t rowb = (size_t)c * NPIX + n0;
            const float4 xv0 = *(const float4*)&Xb[rowb + tx * 4];
            const float4 xv1 = *(const float4*)&Xb[rowb + 64 + tx * 4];
            const float4 o0 = make_float4(acc[r][0] + xv0.x, acc[r][1] + xv0.y,
                                          acc[r][2] + xv0.z, acc[r][3] + xv0.w);
            const float4 o1 = make_float4(acc[r][4] + xv1.x, acc[r][5] + xv1.y,
                                          acc[r][6] + xv1.z, acc[r][7] + xv1.w);
            *(float4*)&Ob[rowb + tx * 4]      = o0;
            *(float4*)&Ob[rowb + 64 + tx * 4] = o1;
        }
}

// ===========================================================================
// launch
// ===========================================================================
extern "C" void kernel_launch(void* const* d_in, const int* in_sizes, int n_in,
                              void* d_out, int out_size)
{
    (void)in_sizes; (void)n_in; (void)out_size;
    const float* x1  = (const float*)d_in[0];
    const float* x2  = (const float*)d_in[1];
    const float* Wq  = (const float*)d_in[2];
    const float* bq  = (const float*)d_in[3];
    const float* Wk  = (const float*)d_in[4];
    const float* bk  = (const float*)d_in[5];
    const float* Wv1 = (const float*)d_in[6];
    const float* bv1 = (const float*)d_in[7];
    const float* Wv2 = (const float*)d_in[8];
    const float* bv2 = (const float*)d_in[9];

    float* out = (float*)d_out;
    float* att = out + (size_t)2 * BATCH * CH * NPIX;  // attention region

    qk_kernel<<<dim3(NPIX / 32, BATCH), 256>>>(x1, x2, Wq, bq, Wk, bk);
    v_gemm_kernel<<<dim3(NPIX / BN, CH / BM, BATCH * 2), 256>>>(x1, x2, Wv1, bv1, Wv2, bv2);
    attn_kernel<<<dim3(NPIX / 32, BATCH), 256>>>(att);
    out_gemm_kernel<<<dim3(NPIX / BN, CH / BM, BATCH * 2), 256>>>(x1, x2, att, out);
}

// round 8
// speedup vs baseline: 1.5250x; 1.5250x over previous
#include <cuda_runtime.h>
#include <cstdint>

// ---------------------------------------------------------------------------
// SpatialCrossAttention — mma.sync tf32 out-bmm (tcgen05 unavailable: harness
// PTX targets compute_100 without the 'a' feature suffix)
//   B=8, C=256, N=4096, DQK=16
//   out layout: [out1 | out2 | attention]
// ---------------------------------------------------------------------------

#define BATCH 8
#define CH    256
#define NPIX  4096
#define DQK   16
#define TWO_C 512

// SIMT GEMM tiling (v projection)
#define BM 128
#define BN 128
#define TK 16
#define PAD 4

// ---- device scratch ----
__device__ float g_q[BATCH * DQK * NPIX];
__device__ float g_k[BATCH * DQK * NPIX];
__device__ float g_v[2][BATCH * CH * NPIX];

// ===========================================================================
// helpers
// ===========================================================================
__device__ __forceinline__ uint32_t smem_u32(const void* p) {
    uint32_t a;
    asm("{ .reg .u64 t; cvta.to.shared.u64 t, %1; cvt.u32.u64 %0, t; }" : "=r"(a) : "l"(p));
    return a;
}

#define CP_ASYNC16(dst, src) \
    asm volatile("cp.async.cg.shared.global [%0], [%1], 16;" :: "r"(dst), "l"(src) : "memory")
#define CP_COMMIT() asm volatile("cp.async.commit_group;" ::: "memory")
#define CP_WAIT1()  asm volatile("cp.async.wait_group 1;" ::: "memory")
#define CP_WAIT0()  asm volatile("cp.async.wait_group 0;" ::: "memory")

__device__ __forceinline__ float round_tf32(float f) {
    uint32_t u = __float_as_uint(f), o;
    asm("cvt.rna.tf32.f32 %0, %1;" : "=r"(o) : "r"(u));
    return __uint_as_float(o);
}
__device__ __forceinline__ uint32_t to_tf32(float f) {
    uint32_t o;
    asm("cvt.rna.tf32.f32 %0, %1;" : "=r"(o) : "f"(f));
    return o;
}

__device__ __forceinline__ void mma_tf32(float* c, const uint32_t* a, const uint32_t* b) {
    asm volatile(
        "mma.sync.aligned.m16n8k8.row.col.f32.tf32.tf32.f32 "
        "{%0,%1,%2,%3}, {%4,%5,%6,%7}, {%8,%9}, {%0,%1,%2,%3};"
        : "+f"(c[0]), "+f"(c[1]), "+f"(c[2]), "+f"(c[3])
        : "r"(a[0]), "r"(a[1]), "r"(a[2]), "r"(a[3]), "r"(b[0]), "r"(b[1]));
}

// ===========================================================================
// Kernel 1: q/k projection
// ===========================================================================
__global__ __launch_bounds__(256) void qk_kernel(
    const float* __restrict__ x1, const float* __restrict__ x2,
    const float* __restrict__ Wq, const float* __restrict__ bq,
    const float* __restrict__ Wk, const float* __restrict__ bk)
{
    __shared__ float xs[64][33];
    __shared__ float wqs[16][64];
    __shared__ float wks[16][64];

    const int n0  = blockIdx.x * 32;
    const int b   = blockIdx.y;
    const int tid = threadIdx.x;
    const int nl  = tid & 31;
    const int dg  = tid >> 5;

    float aq0 = 0.f, aq1 = 0.f, ak0 = 0.f, ak1 = 0.f;

    for (int c0 = 0; c0 < TWO_C; c0 += 64) {
        for (int r = dg; r < 64; r += 8) {
            const int c = c0 + r;
            const float* src = (c < CH) ? x1 : x2;
            xs[r][nl] = src[((size_t)b * CH + (c & (CH - 1))) * NPIX + n0 + nl];
        }
        for (int i = tid; i < 16 * 64; i += 256) {
            const int d = i >> 6, cc = i & 63;
            wqs[d][cc] = Wq[d * TWO_C + c0 + cc];
            wks[d][cc] = Wk[d * TWO_C + c0 + cc];
        }
        __syncthreads();
        #pragma unroll
        for (int cc = 0; cc < 64; cc++) {
            const float xv = xs[cc][nl];
            aq0 = fmaf(wqs[dg    ][cc], xv, aq0);
            aq1 = fmaf(wqs[dg + 8][cc], xv, aq1);
            ak0 = fmaf(wks[dg    ][cc], xv, ak0);
            ak1 = fmaf(wks[dg + 8][cc], xv, ak1);
        }
        __syncthreads();
    }

    const size_t base = (size_t)b * DQK * NPIX + n0 + nl;
    g_q[base + (size_t)(dg    ) * NPIX] = aq0 + bq[dg];
    g_q[base + (size_t)(dg + 8) * NPIX] = aq1 + bq[dg + 8];
    g_k[base + (size_t)(dg    ) * NPIX] = ak0 + bk[dg];
    g_k[base + (size_t)(dg + 8) * NPIX] = ak1 + bk[dg + 8];
}

// ===========================================================================
// Kernel 2: v projection GEMM (SIMT fp32; epilogue rounds V to tf32-RNA)
// ===========================================================================
__global__ __launch_bounds__(256, 2) void v_gemm_kernel(
    const float* __restrict__ x1, const float* __restrict__ x2,
    const float* __restrict__ Wv1, const float* __restrict__ bv1,
    const float* __restrict__ Wv2, const float* __restrict__ bv2)
{
    __shared__ float As[2][TK][BM + PAD];
    __shared__ float Bs[2][TK][BN + PAD];

    const int which = blockIdx.z & 1;
    const int b     = blockIdx.z >> 1;
    const float* __restrict__ Wv = which ? Wv2 : Wv1;
    const float* __restrict__ bv = which ? bv2 : bv1;
    const float* __restrict__ Xb = (which ? x2 : x1) + (size_t)b * CH * NPIX;
    float* __restrict__ V        = g_v[which] + (size_t)b * CH * NPIX;

    const int n0  = blockIdx.x * BN;
    const int o0  = blockIdx.y * BM;
    const int tid = threadIdx.x;
    const int tx  = tid & 15, ty = tid >> 4;

    const int ar  = tid >> 2;
    const int ak  = (tid & 3) << 2;
    const int bkr = tid >> 5;
    const int bj  = (tid & 31) << 2;

    float acc[8][8];
    #pragma unroll
    for (int r = 0; r < 8; r++)
        #pragma unroll
        for (int s = 0; s < 8; s++) acc[r][s] = 0.f;

    const int KT = CH / TK;
    float4 a0n, a1n, b0n, b1n;

    {
        const float* ap = Wv + (o0 + ar) * CH + ak;
        a0n = *(const float4*)ap;
        a1n = *(const float4*)(ap + 64 * CH);
        const float* bp = Xb + (size_t)bkr * NPIX + n0 + bj;
        b0n = *(const float4*)bp;
        b1n = *(const float4*)(bp + (size_t)8 * NPIX);
        As[0][ak + 0][ar] = a0n.x; As[0][ak + 1][ar] = a0n.y;
        As[0][ak + 2][ar] = a0n.z; As[0][ak + 3][ar] = a0n.w;
        As[0][ak + 0][ar + 64] = a1n.x; As[0][ak + 1][ar + 64] = a1n.y;
        As[0][ak + 2][ar + 64] = a1n.z; As[0][ak + 3][ar + 64] = a1n.w;
        *(float4*)&Bs[0][bkr    ][bj] = b0n;
        *(float4*)&Bs[0][bkr + 8][bj] = b1n;
    }
    __syncthreads();

    for (int kt = 0; kt < KT; kt++) {
        const int cur = kt & 1;
        const bool pf = (kt + 1 < KT);
        if (pf) {
            const int kc = (kt + 1) * TK;
            const float* ap = Wv + (o0 + ar) * CH + kc + ak;
            a0n = *(const float4*)ap;
            a1n = *(const float4*)(ap + 64 * CH);
            const float* bp = Xb + (size_t)(kc + bkr) * NPIX + n0 + bj;
            b0n = *(const float4*)bp;
            b1n = *(const float4*)(bp + (size_t)8 * NPIX);
        }
        #pragma unroll
        for (int k = 0; k < TK; k++) {
            const float4 a0 = *(const float4*)&As[cur][k][ty * 4];
            const float4 a1 = *(const float4*)&As[cur][k][64 + ty * 4];
            const float4 b0 = *(const float4*)&Bs[cur][k][tx * 4];
            const float4 b1 = *(const float4*)&Bs[cur][k][64 + tx * 4];
            const float av[8] = {a0.x, a0.y, a0.z, a0.w, a1.x, a1.y, a1.z, a1.w};
            const float bw[8] = {b0.x, b0.y, b0.z, b0.w, b1.x, b1.y, b1.z, b1.w};
            #pragma unroll
            for (int r = 0; r < 8; r++)
                #pragma unroll
                for (int s = 0; s < 8; s++)
                    acc[r][s] = fmaf(av[r], bw[s], acc[r][s]);
        }
        if (pf) {
            const int nb = cur ^ 1;
            As[nb][ak + 0][ar] = a0n.x; As[nb][ak + 1][ar] = a0n.y;
            As[nb][ak + 2][ar] = a0n.z; As[nb][ak + 3][ar] = a0n.w;
            As[nb][ak + 0][ar + 64] = a1n.x; As[nb][ak + 1][ar + 64] = a1n.y;
            As[nb][ak + 2][ar + 64] = a1n.z; As[nb][ak + 3][ar + 64] = a1n.w;
            *(float4*)&Bs[nb][bkr    ][bj] = b0n;
            *(float4*)&Bs[nb][bkr + 8][bj] = b1n;
        }
        __syncthreads();
    }

    #pragma unroll
    for (int rg = 0; rg < 2; rg++)
        #pragma unroll
        for (int rr = 0; rr < 4; rr++) {
            const int r = rg * 4 + rr;
            const int o = o0 + rg * 64 + ty * 4 + rr;
            const float bias = __ldg(&bv[o]);
            float* dst = V + (size_t)o * NPIX + n0;
            const float4 v0 = make_float4(round_tf32(acc[r][0] + bias), round_tf32(acc[r][1] + bias),
                                          round_tf32(acc[r][2] + bias), round_tf32(acc[r][3] + bias));
            const float4 v1 = make_float4(round_tf32(acc[r][4] + bias), round_tf32(acc[r][5] + bias),
                                          round_tf32(acc[r][6] + bias), round_tf32(acc[r][7] + bias));
            *(float4*)(dst + tx * 4)      = v0;
            *(float4*)(dst + 64 + tx * 4) = v1;
        }
}

// ===========================================================================
// Kernel 3: energy + softmax
// ===========================================================================
__global__ __launch_bounds__(256) void attn_kernel(float* __restrict__ att)
{
    __shared__ float ks[16][256];
    __shared__ float qs[16][32];
    __shared__ float s_mx[32];
    __shared__ float s_inv[32];

    const int n0   = blockIdx.x * 32;
    const int b    = blockIdx.y;
    const int tid  = threadIdx.x;
    const int lane = tid & 31;
    const int w    = tid >> 5;
    const int rb   = w * 4;

    const float* __restrict__ qb = g_q + (size_t)b * DQK * NPIX;
    const float* __restrict__ kb = g_k + (size_t)b * DQK * NPIX;
    float* __restrict__ attb     = att + (size_t)b * NPIX * NPIX;

    for (int i = tid; i < 512; i += 256) {
        const int d = i >> 5, nl = i & 31;
        qs[d][nl] = qb[(size_t)d * NPIX + n0 + nl];
    }
    __syncthreads();
    float qr[4][16];
    #pragma unroll
    for (int rr = 0; rr < 4; rr++)
        #pragma unroll
        for (int d = 0; d < 16; d++)
            qr[rr][d] = qs[d][rb + rr];

    float mx[4], sm[4];
    #pragma unroll
    for (int rr = 0; rr < 4; rr++) { mx[rr] = -1e30f; sm[rr] = 0.f; }

    for (int m0 = 0; m0 < NPIX; m0 += 256) {
        __syncthreads();
        #pragma unroll
        for (int r = 0; r < 4; r++) {
            const int lin = tid + 256 * r;
            const int d = lin >> 6, mm4 = (lin & 63) << 2;
            *(float4*)&ks[d][mm4] = *(const float4*)&kb[(size_t)d * NPIX + m0 + mm4];
        }
        __syncthreads();
        #pragma unroll
        for (int it = 0; it < 8; it++) {
            const int mm = lane + it * 32;
            float e0 = 0.f, e1 = 0.f, e2 = 0.f, e3 = 0.f;
            #pragma unroll
            for (int d = 0; d < 16; d++) {
                const float kv = ks[d][mm];
                e0 = fmaf(qr[0][d], kv, e0);
                e1 = fmaf(qr[1][d], kv, e1);
                e2 = fmaf(qr[2][d], kv, e2);
                e3 = fmaf(qr[3][d], kv, e3);
            }
            { const float dd = e0 - mx[0]; if (dd > 0.f) { sm[0] = sm[0] * __expf(-dd) + 1.f; mx[0] = e0; } else sm[0] += __expf(dd); }
            { const float dd = e1 - mx[1]; if (dd > 0.f) { sm[1] = sm[1] * __expf(-dd) + 1.f; mx[1] = e1; } else sm[1] += __expf(dd); }
            { const float dd = e2 - mx[2]; if (dd > 0.f) { sm[2] = sm[2] * __expf(-dd) + 1.f; mx[2] = e2; } else sm[2] += __expf(dd); }
            { const float dd = e3 - mx[3]; if (dd > 0.f) { sm[3] = sm[3] * __expf(-dd) + 1.f; mx[3] = e3; } else sm[3] += __expf(dd); }
        }
    }

    #pragma unroll
    for (int rr = 0; rr < 4; rr++) {
        float m = mx[rr], s = sm[rr];
        #pragma unroll
        for (int off = 16; off; off >>= 1) {
            const float om = __shfl_xor_sync(0xffffffffu, m, off);
            const float os = __shfl_xor_sync(0xffffffffu, s, off);
            const float nm = fmaxf(m, om);
            s = s * __expf(m - nm) + os * __expf(om - nm);
            m = nm;
        }
        if (lane == 0) { s_mx[rb + rr] = m; s_inv[rb + rr] = 1.f / s; }
    }
    __syncthreads();
    float fm[4], fi[4];
    #pragma unroll
    for (int rr = 0; rr < 4; rr++) { fm[rr] = s_mx[rb + rr]; fi[rr] = s_inv[rb + rr]; }

    for (int m0 = 0; m0 < NPIX; m0 += 256) {
        __syncthreads();
        #pragma unroll
        for (int r = 0; r < 4; r++) {
            const int lin = tid + 256 * r;
            const int d = lin >> 6, mm4 = (lin & 63) << 2;
            *(float4*)&ks[d][mm4] = *(const float4*)&kb[(size_t)d * NPIX + m0 + mm4];
        }
        __syncthreads();
        #pragma unroll
        for (int it = 0; it < 8; it++) {
            const int mm = lane + it * 32;
            float e0 = 0.f, e1 = 0.f, e2 = 0.f, e3 = 0.f;
            #pragma unroll
            for (int d = 0; d < 16; d++) {
                const float kv = ks[d][mm];
                e0 = fmaf(qr[0][d], kv, e0);
                e1 = fmaf(qr[1][d], kv, e1);
                e2 = fmaf(qr[2][d], kv, e2);
                e3 = fmaf(qr[3][d], kv, e3);
            }
            attb[(size_t)(n0 + rb + 0) * NPIX + m0 + mm] = __expf(e0 - fm[0]) * fi[0];
            attb[(size_t)(n0 + rb + 1) * NPIX + m0 + mm] = __expf(e1 - fm[1]) * fi[1];
            attb[(size_t)(n0 + rb + 2) * NPIX + m0 + mm] = __expf(e2 - fm[2]) * fi[2];
            attb[(size_t)(n0 + rb + 3) * NPIX + m0 + mm] = __expf(e3 - fm[3]) * fi[3];
        }
    }
}

// ===========================================================================
// Kernel 4: out-bmm via mma.sync tf32.
//   D[c, n] = sum_m V[c, m] * Att[n, m]; out = D + x.
//   Block tile 128(c) x 256(n), BK=16, 3-stage cp.async pipeline.
//   8 warps (2 x 4), 64x64 warp tiles of m16n8k8 tf32 MMAs.
//   Smem row stride 28 floats: 16B-aligned cp.async dsts + conflict-free frags.
// ===========================================================================
#define OBM 128
#define OBN 256
#define OBK 16
#define OSTRIDE 28
#define A_FLOATS (OBM * OSTRIDE)                 // 3584
#define STAGE_FLOATS ((OBM + OBN) * OSTRIDE)     // 10752
#define ONSTAGE 3
#define OSMEM_BYTES (ONSTAGE * STAGE_FLOATS * 4) // 129024

__global__ __launch_bounds__(256, 1) void out_gemm_mma(
    const float* __restrict__ x1, const float* __restrict__ x2,
    const float* __restrict__ att, float* __restrict__ out)
{
    extern __shared__ float sm[];

    const int tid  = threadIdx.x;
    const int wid  = tid >> 5;
    const int lane = tid & 31;
    const int grp  = lane >> 2;    // 0..7
    const int tig  = lane & 3;     // 0..3
    const int wm   = wid >> 2;     // 0..1 -> m offset 64*wm
    const int wn   = wid & 3;      // 0..3 -> n offset 64*wn

    const int which = blockIdx.z & 1;
    const int b     = blockIdx.z >> 1;
    const int n0    = blockIdx.x * OBN;
    const int c0    = blockIdx.y * OBM;

    const float* __restrict__ Vb = g_v[which] + (size_t)b * CH * NPIX;
    const float* __restrict__ Ab = att + (size_t)b * NPIX * NPIX;

    // ---- producer mapping ----
    const int a_row = tid >> 1;
    const int a_k0  = (tid & 1) * 8;
    const float* aSrc = Vb + (size_t)(c0 + a_row) * NPIX + a_k0;
    const float* bSrc = Ab + (size_t)(n0 + tid) * NPIX;

    const uint32_t smb = smem_u32(sm);
    uint32_t aDst[2], bDst[4];
    #pragma unroll
    for (int i = 0; i < 2; i++)
        aDst[i] = smb + (uint32_t)(a_row * OSTRIDE + a_k0 + i * 4) * 4u;
    #pragma unroll
    for (int i = 0; i < 4; i++)
        bDst[i] = smb + (uint32_t)(A_FLOATS + tid * OSTRIDE + i * 4) * 4u;

    float acc[4][8][4];
    #pragma unroll
    for (int mt = 0; mt < 4; mt++)
        #pragma unroll
        for (int nt = 0; nt < 8; nt++)
            #pragma unroll
            for (int q = 0; q < 4; q++) acc[mt][nt][q] = 0.f;

    const int KT = NPIX / OBK;   // 256

    // prologue: stages 0, 1
    #pragma unroll
    for (int s = 0; s < ONSTAGE - 1; s++) {
        const uint32_t so = (uint32_t)(s * STAGE_FLOATS * 4);
        const int kc = s * OBK;
        #pragma unroll
        for (int i = 0; i < 2; i++) CP_ASYNC16(aDst[i] + so, aSrc + kc + i * 4);
        #pragma unroll
        for (int i = 0; i < 4; i++) CP_ASYNC16(bDst[i] + so, bSrc + kc + i * 4);
        CP_COMMIT();
    }

    // fragment base pointers (per-warp)
    const float* As_base = sm + (size_t)(wm * 64 + grp) * OSTRIDE;
    const float* Bs_base = sm + A_FLOATS + (size_t)(wn * 64 + grp) * OSTRIDE;

    for (int kt = 0; kt < KT; kt++) {
        CP_WAIT1();
        __syncthreads();

        // issue stage kt+2 (overwrites buffer of kt-1, all compute done)
        const int nk = kt + ONSTAGE - 1;
        if (nk < KT) {
            const uint32_t so = (uint32_t)((nk % ONSTAGE) * STAGE_FLOATS * 4);
            const int kc = nk * OBK;
            #pragma unroll
            for (int i = 0; i < 2; i++) CP_ASYNC16(aDst[i] + so, aSrc + kc + i * 4);
            #pragma unroll
            for (int i = 0; i < 4; i++) CP_ASYNC16(bDst[i] + so, bSrc + kc + i * 4);
        }
        CP_COMMIT();

        // compute on stage kt%3
        const int cur = kt % ONSTAGE;
        const float* Asb = As_base + (size_t)cur * STAGE_FLOATS;
        const float* Bsb = Bs_base + (size_t)cur * STAGE_FLOATS;

        #pragma unroll
        for (int ks = 0; ks < 2; ks++) {
            const int kk = ks * 8 + tig;
            uint32_t afr[4][4];
            #pragma unroll
            for (int mt = 0; mt < 4; mt++) {
                const float* ap = Asb + (size_t)(mt * 16) * OSTRIDE;
                afr[mt][0] = __float_as_uint(ap[kk]);
                afr[mt][1] = __float_as_uint(ap[8 * OSTRIDE + kk]);
                afr[mt][2] = __float_as_uint(ap[kk + 4]);
                afr[mt][3] = __float_as_uint(ap[8 * OSTRIDE + kk + 4]);
            }
            uint32_t bfr[8][2];
            #pragma unroll
            for (int nt = 0; nt < 8; nt++) {
                const float* bp = Bsb + (size_t)(nt * 8) * OSTRIDE;
                bfr[nt][0] = to_tf32(bp[kk]);
                bfr[nt][1] = to_tf32(bp[kk + 4]);
            }
            #pragma unroll
            for (int mt = 0; mt < 4; mt++)
                #pragma unroll
                for (int nt = 0; nt < 8; nt++)
                    mma_tf32(acc[mt][nt], afr[mt], bfr[nt]);
        }
        __syncthreads();
    }
    CP_WAIT0();

    // ---- epilogue: + residual x, store ----
    const float* __restrict__ Xb = (which ? x2 : x1) + (size_t)b * CH * NPIX;
    float* __restrict__ Ob = out + (size_t)which * BATCH * CH * NPIX + (size_t)b * CH * NPIX;

    #pragma unroll
    for (int mt = 0; mt < 4; mt++) {
        const int row0 = c0 + wm * 64 + mt * 16 + grp;
        const size_t r0b = (size_t)row0 * NPIX;
        const size_t r1b = (size_t)(row0 + 8) * NPIX;
        #pragma unroll
        for (int nt = 0; nt < 8; nt++) {
            const int col = n0 + wn * 64 + nt * 8 + tig * 2;
            const float2 x0 = *(const float2*)&Xb[r0b + col];
            const float2 x1v = *(const float2*)&Xb[r1b + col];
            float2 o0, o1;
            o0.x = acc[mt][nt][0] + x0.x;  o0.y = acc[mt][nt][1] + x0.y;
            o1.x = acc[mt][nt][2] + x1v.x; o1.y = acc[mt][nt][3] + x1v.y;
            *(float2*)&Ob[r0b + col] = o0;
            *(float2*)&Ob[r1b + col] = o1;
        }
    }
}

// ===========================================================================
// launch
// ===========================================================================
extern "C" void kernel_launch(void* const* d_in, const int* in_sizes, int n_in,
                              void* d_out, int out_size)
{
    (void)in_sizes; (void)n_in; (void)out_size;
    const float* x1  = (const float*)d_in[0];
    const float* x2  = (const float*)d_in[1];
    const float* Wq  = (const float*)d_in[2];
    const float* bq  = (const float*)d_in[3];
    const float* Wk  = (const float*)d_in[4];
    const float* bk  = (const float*)d_in[5];
    const float* Wv1 = (const float*)d_in[6];
    const float* bv1 = (const float*)d_in[7];
    const float* Wv2 = (const float*)d_in[8];
    const float* bv2 = (const float*)d_in[9];

    float* out = (float*)d_out;
    float* att = out + (size_t)2 * BATCH * CH * NPIX;

    cudaFuncSetAttribute(out_gemm_mma, cudaFuncAttributeMaxDynamicSharedMemorySize, OSMEM_BYTES);

    qk_kernel<<<dim3(NPIX / 32, BATCH), 256>>>(x1, x2, Wq, bq, Wk, bk);
    v_gemm_kernel<<<dim3(NPIX / BN, CH / BM, BATCH * 2), 256>>>(x1, x2, Wv1, bv1, Wv2, bv2);
    attn_kernel<<<dim3(NPIX / 32, BATCH), 256>>>(att);
    out_gemm_mma<<<dim3(NPIX / OBN, CH / OBM, BATCH * 2), 256, OSMEM_BYTES>>>(x1, x2, att, out);
}

// round 10
// speedup vs baseline: 2.3704x; 1.5544x over previous
#include <cuda_runtime.h>
#include <cuda_fp16.h>
#include <cstdint>

// ---------------------------------------------------------------------------
// SpatialCrossAttention — fp16 HMMA out-bmm with ldmatrix fragments
//   B=8, C=256, N=4096, DQK=16
//   out layout: [out1 | out2 | attention]
// ---------------------------------------------------------------------------

#define BATCH 8
#define CH    256
#define NPIX  4096
#define DQK   16
#define TWO_C 512

// SIMT GEMM tiling (v projection)
#define BM 128
#define BN 128
#define TK 16
#define PAD 4

// ---- device scratch ----
__device__ float  g_q[BATCH * DQK * NPIX];
__device__ float  g_k[BATCH * DQK * NPIX];
__device__ __half g_v_h[2][BATCH * CH * NPIX];            // 32 MB
__device__ __half g_att_h[(size_t)BATCH * NPIX * NPIX];   // 256 MB

// ===========================================================================
// helpers
// ===========================================================================
__device__ __forceinline__ uint32_t smem_u32(const void* p) {
    uint32_t a;
    asm("{ .reg .u64 t; cvta.to.shared.u64 t, %1; cvt.u32.u64 %0, t; }" : "=r"(a) : "l"(p));
    return a;
}

__device__ __forceinline__ uint32_t pack_h2(float lo, float hi) {
    __half2 h = __floats2half2_rn(lo, hi);
    return *(uint32_t*)&h;
}

#define CP_ASYNC16(dst, src) \
    asm volatile("cp.async.cg.shared.global [%0], [%1], 16;" :: "r"(dst), "l"(src) : "memory")
#define CP_COMMIT() asm volatile("cp.async.commit_group;" ::: "memory")
#define CP_WAIT2()  asm volatile("cp.async.wait_group 2;" ::: "memory")
#define CP_WAIT0()  asm volatile("cp.async.wait_group 0;" ::: "memory")

#define LDSM_X4(r0, r1, r2, r3, addr) \
    asm volatile("ldmatrix.sync.aligned.m8n8.x4.shared.b16 {%0,%1,%2,%3}, [%4];" \
                 : "=r"(r0), "=r"(r1), "=r"(r2), "=r"(r3) : "r"(addr))

__device__ __forceinline__ void mma_f16(float* c, const uint32_t* a, const uint32_t* b) {
    asm volatile(
        "mma.sync.aligned.m16n8k16.row.col.f32.f16.f16.f32 "
        "{%0,%1,%2,%3}, {%4,%5,%6,%7}, {%8,%9}, {%0,%1,%2,%3};"
        : "+f"(c[0]), "+f"(c[1]), "+f"(c[2]), "+f"(c[3])
        : "r"(a[0]), "r"(a[1]), "r"(a[2]), "r"(a[3]), "r"(b[0]), "r"(b[1]));
}

// ===========================================================================
// Kernel 1: q/k projection
// ===========================================================================
__global__ __launch_bounds__(256) void qk_kernel(
    const float* __restrict__ x1, const float* __restrict__ x2,
    const float* __restrict__ Wq, const float* __restrict__ bq,
    const float* __restrict__ Wk, const float* __restrict__ bk)
{
    __shared__ float xs[64][33];
    __shared__ float wqs[16][64];
    __shared__ float wks[16][64];

    const int n0  = blockIdx.x * 32;
    const int b   = blockIdx.y;
    const int tid = threadIdx.x;
    const int nl  = tid & 31;
    const int dg  = tid >> 5;

    float aq0 = 0.f, aq1 = 0.f, ak0 = 0.f, ak1 = 0.f;

    for (int c0 = 0; c0 < TWO_C; c0 += 64) {
        for (int r = dg; r < 64; r += 8) {
            const int c = c0 + r;
            const float* src = (c < CH) ? x1 : x2;
            xs[r][nl] = src[((size_t)b * CH + (c & (CH - 1))) * NPIX + n0 + nl];
        }
        for (int i = tid; i < 16 * 64; i += 256) {
            const int d = i >> 6, cc = i & 63;
            wqs[d][cc] = Wq[d * TWO_C + c0 + cc];
            wks[d][cc] = Wk[d * TWO_C + c0 + cc];
        }
        __syncthreads();
        #pragma unroll
        for (int cc = 0; cc < 64; cc++) {
            const float xv = xs[cc][nl];
            aq0 = fmaf(wqs[dg    ][cc], xv, aq0);
            aq1 = fmaf(wqs[dg + 8][cc], xv, aq1);
            ak0 = fmaf(wks[dg    ][cc], xv, ak0);
            ak1 = fmaf(wks[dg + 8][cc], xv, ak1);
        }
        __syncthreads();
    }

    const size_t base = (size_t)b * DQK * NPIX + n0 + nl;
    g_q[base + (size_t)(dg    ) * NPIX] = aq0 + bq[dg];
    g_q[base + (size_t)(dg + 8) * NPIX] = aq1 + bq[dg + 8];
    g_k[base + (size_t)(dg    ) * NPIX] = ak0 + bk[dg];
    g_k[base + (size_t)(dg + 8) * NPIX] = ak1 + bk[dg + 8];
}

// ===========================================================================
// Kernel 2: v projection GEMM (SIMT fp32; epilogue stores V as fp16)
// ===========================================================================
__global__ __launch_bounds__(256, 2) void v_gemm_kernel(
    const float* __restrict__ x1, const float* __restrict__ x2,
    const float* __restrict__ Wv1, const float* __restrict__ bv1,
    const float* __restrict__ Wv2, const float* __restrict__ bv2)
{
    __shared__ float As[2][TK][BM + PAD];
    __shared__ float Bs[2][TK][BN + PAD];

    const int which = blockIdx.z & 1;
    const int b     = blockIdx.z >> 1;
    const float* __restrict__ Wv = which ? Wv2 : Wv1;
    const float* __restrict__ bv = which ? bv2 : bv1;
    const float* __restrict__ Xb = (which ? x2 : x1) + (size_t)b * CH * NPIX;
    __half* __restrict__ V       = g_v_h[which] + (size_t)b * CH * NPIX;

    const int n0  = blockIdx.x * BN;
    const int o0  = blockIdx.y * BM;
    const int tid = threadIdx.x;
    const int tx  = tid & 15, ty = tid >> 4;

    const int ar  = tid >> 2;
    const int ak  = (tid & 3) << 2;
    const int bkr = tid >> 5;
    const int bj  = (tid & 31) << 2;

    float acc[8][8];
    #pragma unroll
    for (int r = 0; r < 8; r++)
        #pragma unroll
        for (int s = 0; s < 8; s++) acc[r][s] = 0.f;

    const int KT = CH / TK;
    float4 a0n, a1n, b0n, b1n;

    {
        const float* ap = Wv + (o0 + ar) * CH + ak;
        a0n = *(const float4*)ap;
        a1n = *(const float4*)(ap + 64 * CH);
        const float* bp = Xb + (size_t)bkr * NPIX + n0 + bj;
        b0n = *(const float4*)bp;
        b1n = *(const float4*)(bp + (size_t)8 * NPIX);
        As[0][ak + 0][ar] = a0n.x; As[0][ak + 1][ar] = a0n.y;
        As[0][ak + 2][ar] = a0n.z; As[0][ak + 3][ar] = a0n.w;
        As[0][ak + 0][ar + 64] = a1n.x; As[0][ak + 1][ar + 64] = a1n.y;
        As[0][ak + 2][ar + 64] = a1n.z; As[0][ak + 3][ar + 64] = a1n.w;
        *(float4*)&Bs[0][bkr    ][bj] = b0n;
        *(float4*)&Bs[0][bkr + 8][bj] = b1n;
    }
    __syncthreads();

    for (int kt = 0; kt < KT; kt++) {
        const int cur = kt & 1;
        const bool pf = (kt + 1 < KT);
        if (pf) {
            const int kc = (kt + 1) * TK;
            const float* ap = Wv + (o0 + ar) * CH + kc + ak;
            a0n = *(const float4*)ap;
            a1n = *(const float4*)(ap + 64 * CH);
            const float* bp = Xb + (size_t)(kc + bkr) * NPIX + n0 + bj;
            b0n = *(const float4*)bp;
            b1n = *(const float4*)(bp + (size_t)8 * NPIX);
        }
        #pragma unroll
        for (int k = 0; k < TK; k++) {
            const float4 a0 = *(const float4*)&As[cur][k][ty * 4];
            const float4 a1 = *(const float4*)&As[cur][k][64 + ty * 4];
            const float4 b0 = *(const float4*)&Bs[cur][k][tx * 4];
            const float4 b1 = *(const float4*)&Bs[cur][k][64 + tx * 4];
            const float av[8] = {a0.x, a0.y, a0.z, a0.w, a1.x, a1.y, a1.z, a1.w};
            const float bw[8] = {b0.x, b0.y, b0.z, b0.w, b1.x, b1.y, b1.z, b1.w};
            #pragma unroll
            for (int r = 0; r < 8; r++)
                #pragma unroll
                for (int s = 0; s < 8; s++)
                    acc[r][s] = fmaf(av[r], bw[s], acc[r][s]);
        }
        if (pf) {
            const int nb = cur ^ 1;
            As[nb][ak + 0][ar] = a0n.x; As[nb][ak + 1][ar] = a0n.y;
            As[nb][ak + 2][ar] = a0n.z; As[nb][ak + 3][ar] = a0n.w;
            As[nb][ak + 0][ar + 64] = a1n.x; As[nb][ak + 1][ar + 64] = a1n.y;
            As[nb][ak + 2][ar + 64] = a1n.z; As[nb][ak + 3][ar + 64] = a1n.w;
            *(float4*)&Bs[nb][bkr    ][bj] = b0n;
            *(float4*)&Bs[nb][bkr + 8][bj] = b1n;
        }
        __syncthreads();
    }

    #pragma unroll
    for (int rg = 0; rg < 2; rg++)
        #pragma unroll
        for (int rr = 0; rr < 4; rr++) {
            const int r = rg * 4 + rr;
            const int o = o0 + rg * 64 + ty * 4 + rr;
            const float bias = __ldg(&bv[o]);
            __half* dst = V + (size_t)o * NPIX + n0;
            uint2 h0, h1;
            h0.x = pack_h2(acc[r][0] + bias, acc[r][1] + bias);
            h0.y = pack_h2(acc[r][2] + bias, acc[r][3] + bias);
            h1.x = pack_h2(acc[r][4] + bias, acc[r][5] + bias);
            h1.y = pack_h2(acc[r][6] + bias, acc[r][7] + bias);
            *(uint2*)(dst + tx * 4)      = h0;
            *(uint2*)(dst + 64 + tx * 4) = h1;
        }
}

// ===========================================================================
// Kernel 3: energy + softmax -> fp32 attention (d_out) + fp16 copy (scratch)
// ===========================================================================
__global__ __launch_bounds__(256) void attn_kernel(float* __restrict__ att)
{
    __shared__ float ks[16][256];
    __shared__ float qs[16][32];
    __shared__ float s_mx[32];
    __shared__ float s_inv[32];

    const int n0   = blockIdx.x * 32;
    const int b    = blockIdx.y;
    const int tid  = threadIdx.x;
    const int lane = tid & 31;
    const int w    = tid >> 5;
    const int rb   = w * 4;

    const float* __restrict__ qb = g_q + (size_t)b * DQK * NPIX;
    const float* __restrict__ kb = g_k + (size_t)b * DQK * NPIX;
    float* __restrict__ attb     = att + (size_t)b * NPIX * NPIX;
    __half* __restrict__ atth    = g_att_h + (size_t)b * NPIX * NPIX;

    for (int i = tid; i < 512; i += 256) {
        const int d = i >> 5, nl = i & 31;
        qs[d][nl] = qb[(size_t)d * NPIX + n0 + nl];
    }
    __syncthreads();
    float qr[4][16];
    #pragma unroll
    for (int rr = 0; rr < 4; rr++)
        #pragma unroll
        for (int d = 0; d < 16; d++)
            qr[rr][d] = qs[d][rb + rr];

    float mx[4], sm[4];
    #pragma unroll
    for (int rr = 0; rr < 4; rr++) { mx[rr] = -1e30f; sm[rr] = 0.f; }

    for (int m0 = 0; m0 < NPIX; m0 += 256) {
        __syncthreads();
        #pragma unroll
        for (int r = 0; r < 4; r++) {
            const int lin = tid + 256 * r;
            const int d = lin >> 6, mm4 = (lin & 63) << 2;
            *(float4*)&ks[d][mm4] = *(const float4*)&kb[(size_t)d * NPIX + m0 + mm4];
        }
        __syncthreads();
        #pragma unroll
        for (int it = 0; it < 8; it++) {
            const int mm = lane + it * 32;
            float e0 = 0.f, e1 = 0.f, e2 = 0.f, e3 = 0.f;
            #pragma unroll
            for (int d = 0; d < 16; d++) {
                const float kv = ks[d][mm];
                e0 = fmaf(qr[0][d], kv, e0);
                e1 = fmaf(qr[1][d], kv, e1);
                e2 = fmaf(qr[2][d], kv, e2);
                e3 = fmaf(qr[3][d], kv, e3);
            }
            { const float dd = e0 - mx[0]; if (dd > 0.f) { sm[0] = sm[0] * __expf(-dd) + 1.f; mx[0] = e0; } else sm[0] += __expf(dd); }
            { const float dd = e1 - mx[1]; if (dd > 0.f) { sm[1] = sm[1] * __expf(-dd) + 1.f; mx[1] = e1; } else sm[1] += __expf(dd); }
            { const float dd = e2 - mx[2]; if (dd > 0.f) { sm[2] = sm[2] * __expf(-dd) + 1.f; mx[2] = e2; } else sm[2] += __expf(dd); }
            { const float dd = e3 - mx[3]; if (dd > 0.f) { sm[3] = sm[3] * __expf(-dd) + 1.f; mx[3] = e3; } else sm[3] += __expf(dd); }
        }
    }

    #pragma unroll
    for (int rr = 0; rr < 4; rr++) {
        float m = mx[rr], s = sm[rr];
        #pragma unroll
        for (int off = 16; off; off >>= 1) {
            const float om = __shfl_xor_sync(0xffffffffu, m, off);
            const float os = __shfl_xor_sync(0xffffffffu, s, off);
            const float nm = fmaxf(m, om);
            s = s * __expf(m - nm) + os * __expf(om - nm);
            m = nm;
        }
        if (lane == 0) { s_mx[rb + rr] = m; s_inv[rb + rr] = 1.f / s; }
    }
    __syncthreads();
    float fm[4], fi[4];
    #pragma unroll
    for (int rr = 0; rr < 4; rr++) { fm[rr] = s_mx[rb + rr]; fi[rr] = s_inv[rb + rr]; }

    for (int m0 = 0; m0 < NPIX; m0 += 256) {
        __syncthreads();
        #pragma unroll
        for (int r = 0; r < 4; r++) {
            const int lin = tid + 256 * r;
            const int d = lin >> 6, mm4 = (lin & 63) << 2;
            *(float4*)&ks[d][mm4] = *(const float4*)&kb[(size_t)d * NPIX + m0 + mm4];
        }
        __syncthreads();
        #pragma unroll
        for (int it = 0; it < 8; it++) {
            const int mm = lane + it * 32;
            float e0 = 0.f, e1 = 0.f, e2 = 0.f, e3 = 0.f;
            #pragma unroll
            for (int d = 0; d < 16; d++) {
                const float kv = ks[d][mm];
                e0 = fmaf(qr[0][d], kv, e0);
                e1 = fmaf(qr[1][d], kv, e1);
                e2 = fmaf(qr[2][d], kv, e2);
                e3 = fmaf(qr[3][d], kv, e3);
            }
            const float p0 = __expf(e0 - fm[0]) * fi[0];
            const float p1 = __expf(e1 - fm[1]) * fi[1];
            const float p2 = __expf(e2 - fm[2]) * fi[2];
            const float p3 = __expf(e3 - fm[3]) * fi[3];
            const size_t i0 = (size_t)(n0 + rb + 0) * NPIX + m0 + mm;
            const size_t i1 = (size_t)(n0 + rb + 1) * NPIX + m0 + mm;
            const size_t i2 = (size_t)(n0 + rb + 2) * NPIX + m0 + mm;
            const size_t i3 = (size_t)(n0 + rb + 3) * NPIX + m0 + mm;
            attb[i0] = p0; attb[i1] = p1; attb[i2] = p2; attb[i3] = p3;
            atth[i0] = __float2half_rn(p0); atth[i1] = __float2half_rn(p1);
            atth[i2] = __float2half_rn(p2); atth[i3] = __float2half_rn(p3);
        }
    }
}

// ===========================================================================
// Kernel 4: out-bmm via fp16 HMMA m16n8k16 + ldmatrix.
//   D[c, n] = sum_m Vh[c, m] * AttH[n, m]; out = D + x (fp32).
//   Block 128(c) x 256(n), BK=32 fp16, 4-stage cp.async ring.
//   8 warps (2 x 4), 64x64 warp tiles.
//   Smem rows = 64 B (32 fp16); 16B-chunk swizzle: j ^= (row>>1)&3
//   -> conflict-free for cp.async stores and ldmatrix 8-row phases.
// ===========================================================================
#define HBM_ 128
#define HBN_ 256
#define HBK_ 32
#define H_A_BYTES (HBM_ * 64)                    // 8192
#define H_STAGE   ((HBM_ + HBN_) * 64)           // 24576
#define HNSTAGE   4
#define HSMEM     (HNSTAGE * H_STAGE)            // 98304

__global__ __launch_bounds__(256, 1) void out_gemm_h(
    const float* __restrict__ x1, const float* __restrict__ x2,
    float* __restrict__ out)
{
    extern __shared__ char smraw[];
    const uint32_t smb = smem_u32(smraw);

    const int tid  = threadIdx.x;
    const int wid  = tid >> 5;
    const int lane = tid & 31;
    const int grp  = lane >> 2;
    const int tig  = lane & 3;
    const int wm   = wid >> 2;     // 0..1
    const int wn   = wid & 3;      // 0..3

    const int which = blockIdx.z & 1;
    const int b     = blockIdx.z >> 1;
    const int n0    = blockIdx.x * HBN_;
    const int c0    = blockIdx.y * HBM_;

    const __half* __restrict__ Vb = g_v_h[which] + (size_t)b * CH * NPIX;
    const __half* __restrict__ Ah = g_att_h + (size_t)b * NPIX * NPIX;

    // ---- producer mapping (swizzled 16B chunks) ----
    const int a_row = tid >> 1;
    const int a_j0  = (tid & 1) * 2;
    const int a_sw  = (a_row >> 1) & 3;
    const int b_sw  = (tid >> 1) & 3;
    uint32_t aDst[2], bDst[4];
    #pragma unroll
    for (int i = 0; i < 2; i++)
        aDst[i] = smb + (uint32_t)(a_row * 64 + ((a_j0 + i) ^ a_sw) * 16);
    #pragma unroll
    for (int i = 0; i < 4; i++)
        bDst[i] = smb + (uint32_t)(H_A_BYTES + tid * 64 + (i ^ b_sw) * 16);
    const __half* aSrc = Vb + (size_t)(c0 + a_row) * NPIX + a_j0 * 8;
    const __half* bSrc = Ah + (size_t)(n0 + tid) * NPIX;

    // ---- ldmatrix lane constants ----
    const int radd = lane & 15;          // row within 16-row tile
    const int jA   = lane >> 4;          // chunk half (0/1)
    const int lsw  = (radd >> 1) & 3;
    const uint32_t rowOff = (uint32_t)radd * 64;
    uint32_t cswk[2];
    cswk[0] = (uint32_t)(((0 + jA) ^ lsw) * 16);
    cswk[1] = (uint32_t)(((2 + jA) ^ lsw) * 16);

    float acc[4][8][4];
    #pragma unroll
    for (int mt = 0; mt < 4; mt++)
        #pragma unroll
        for (int nt = 0; nt < 8; nt++)
            #pragma unroll
            for (int q = 0; q < 4; q++) acc[mt][nt][q] = 0.f;

    const int KT = NPIX / HBK_;   // 128

    // prologue: stages 0..2
    #pragma unroll
    for (int s = 0; s < HNSTAGE - 1; s++) {
        const uint32_t so = (uint32_t)(s * H_STAGE);
        const int kc = s * HBK_;
        #pragma unroll
        for (int i = 0; i < 2; i++) CP_ASYNC16(aDst[i] + so, aSrc + kc + i * 8);
        #pragma unroll
        for (int i = 0; i < 4; i++) CP_ASYNC16(bDst[i] + so, bSrc + kc + i * 8);
        CP_COMMIT();
    }

    const uint32_t aWarp = smb + (uint32_t)(wm * 64) * 64 + rowOff;
    const uint32_t bWarp = smb + H_A_BYTES + (uint32_t)(wn * 64) * 64 + rowOff;

    for (int kt = 0; kt < KT; kt++) {
        CP_WAIT2();
        __syncthreads();

        const int nk = kt + HNSTAGE - 1;
        if (nk < KT) {
            const uint32_t so = (uint32_t)((nk & (HNSTAGE - 1)) * H_STAGE);
            const int kc = nk * HBK_;
            #pragma unroll
            for (int i = 0; i < 2; i++) CP_ASYNC16(aDst[i] + so, aSrc + kc + i * 8);
            #pragma unroll
            for (int i = 0; i < 4; i++) CP_ASYNC16(bDst[i] + so, bSrc + kc + i * 8);
        }
        CP_COMMIT();

        const uint32_t so = (uint32_t)((kt & (HNSTAGE - 1)) * H_STAGE);
        const uint32_t aB = aWarp + so;
        const uint32_t bB = bWarp + so;

        #pragma unroll
        for (int ksp = 0; ksp < 2; ksp++) {
            uint32_t af[4][4];
            #pragma unroll
            for (int mt = 0; mt < 4; mt++)
                LDSM_X4(af[mt][0], af[mt][1], af[mt][2], af[mt][3],
                        aB + (uint32_t)(mt * 1024) + cswk[ksp]);
            uint32_t bf[8][2];
            #pragma unroll
            for (int ntp = 0; ntp < 4; ntp++) {
                uint32_t q0, q1, q2, q3;
                LDSM_X4(q0, q1, q2, q3, bB + (uint32_t)(ntp * 1024) + cswk[ksp]);
                bf[2 * ntp    ][0] = q0; bf[2 * ntp    ][1] = q2;
                bf[2 * ntp + 1][0] = q1; bf[2 * ntp + 1][1] = q3;
            }
            #pragma unroll
            for (int mt = 0; mt < 4; mt++)
                #pragma unroll
                for (int nt = 0; nt < 8; nt++)
                    mma_f16(acc[mt][nt], af[mt], bf[nt]);
        }
        __syncthreads();
    }
    CP_WAIT0();

    // ---- epilogue: + residual x (fp32), store ----
    const float* __restrict__ Xb = (which ? x2 : x1) + (size_t)b * CH * NPIX;
    float* __restrict__ Ob = out + (size_t)which * BATCH * CH * NPIX + (size_t)b * CH * NPIX;

    #pragma unroll
    for (int mt = 0; mt < 4; mt++) {
        const int row0 = c0 + wm * 64 + mt * 16 + grp;
        const size_t r0b = (size_t)row0 * NPIX;
        const size_t r1b = (size_t)(row0 + 8) * NPIX;
        #pragma unroll
        for (int nt = 0; nt < 8; nt++) {
            const int col = n0 + wn * 64 + nt * 8 + tig * 2;
            const float2 x0 = *(const float2*)&Xb[r0b + col];
            const float2 x1v = *(const float2*)&Xb[r1b + col];
            float2 o0, o1;
            o0.x = acc[mt][nt][0] + x0.x;  o0.y = acc[mt][nt][1] + x0.y;
            o1.x = acc[mt][nt][2] + x1v.x; o1.y = acc[mt][nt][3] + x1v.y;
            *(float2*)&Ob[r0b + col] = o0;
            *(float2*)&Ob[r1b + col] = o1;
        }
    }
}

// ===========================================================================
// launch
// ===========================================================================
extern "C" void kernel_launch(void* const* d_in, const int* in_sizes, int n_in,
                              void* d_out, int out_size)
{
    (void)in_sizes; (void)n_in; (void)out_size;
    const float* x1  = (const float*)d_in[0];
    const float* x2  = (const float*)d_in[1];
    const float* Wq  = (const float*)d_in[2];
    const float* bq  = (const float*)d_in[3];
    const float* Wk  = (const float*)d_in[4];
    const float* bk  = (const float*)d_in[5];
    const float* Wv1 = (const float*)d_in[6];
    const float* bv1 = (const float*)d_in[7];
    const float* Wv2 = (const float*)d_in[8];
    const float* bv2 = (const float*)d_in[9];

    float* out = (float*)d_out;
    float* att = out + (size_t)2 * BATCH * CH * NPIX;

    cudaFuncSetAttribute(out_gemm_h, cudaFuncAttributeMaxDynamicSharedMemorySize, HSMEM);

    qk_kernel<<<dim3(NPIX / 32, BATCH), 256>>>(x1, x2, Wq, bq, Wk, bk);
    v_gemm_kernel<<<dim3(NPIX / BN, CH / BM, BATCH * 2), 256>>>(x1, x2, Wv1, bv1, Wv2, bv2);
    attn_kernel<<<dim3(NPIX / 32, BATCH), 256>>>(att);
    out_gemm_h<<<dim3(NPIX / HBN_, CH / HBM_, BATCH * 2), 256, HSMEM>>>(x1, x2, out);
}

// round 12
// speedup vs baseline: 2.7055x; 1.1414x over previous
#include <cuda_runtime.h>
#include <cuda_fp16.h>
#include <cstdint>

// ---------------------------------------------------------------------------
// SpatialCrossAttention — fp16 HMMA out-bmm, 16-warp CTA for latency hiding
//   B=8, C=256, N=4096, DQK=16
//   out layout: [out1 | out2 | attention]
// ---------------------------------------------------------------------------

#define BATCH 8
#define CH    256
#define NPIX  4096
#define DQK   16
#define TWO_C 512

// SIMT GEMM tiling (v projection)
#define BM 128
#define BN 128
#define TK 16
#define PAD 4

// ---- device scratch ----
__device__ float  g_q[BATCH * DQK * NPIX];
__device__ float  g_k[BATCH * DQK * NPIX];
__device__ __half g_v_h[2][BATCH * CH * NPIX];            // 32 MB
__device__ __half g_att_h[(size_t)BATCH * NPIX * NPIX];   // 256 MB

// ===========================================================================
// helpers
// ===========================================================================
__device__ __forceinline__ uint32_t smem_u32(const void* p) {
    uint32_t a;
    asm("{ .reg .u64 t; cvta.to.shared.u64 t, %1; cvt.u32.u64 %0, t; }" : "=r"(a) : "l"(p));
    return a;
}

__device__ __forceinline__ uint32_t pack_h2(float lo, float hi) {
    __half2 h = __floats2half2_rn(lo, hi);
    return *(uint32_t*)&h;
}

#define CP_ASYNC16(dst, src) \
    asm volatile("cp.async.cg.shared.global [%0], [%1], 16;" :: "r"(dst), "l"(src) : "memory")
#define CP_COMMIT() asm volatile("cp.async.commit_group;" ::: "memory")
#define CP_WAIT2()  asm volatile("cp.async.wait_group 2;" ::: "memory")
#define CP_WAIT0()  asm volatile("cp.async.wait_group 0;" ::: "memory")

#define LDSM_X4(r0, r1, r2, r3, addr) \
    asm volatile("ldmatrix.sync.aligned.m8n8.x4.shared.b16 {%0,%1,%2,%3}, [%4];" \
                 : "=r"(r0), "=r"(r1), "=r"(r2), "=r"(r3) : "r"(addr))

__device__ __forceinline__ void mma_f16(float* c, const uint32_t* a, const uint32_t* b) {
    asm volatile(
        "mma.sync.aligned.m16n8k16.row.col.f32.f16.f16.f32 "
        "{%0,%1,%2,%3}, {%4,%5,%6,%7}, {%8,%9}, {%0,%1,%2,%3};"
        : "+f"(c[0]), "+f"(c[1]), "+f"(c[2]), "+f"(c[3])
        : "r"(a[0]), "r"(a[1]), "r"(a[2]), "r"(a[3]), "r"(b[0]), "r"(b[1]));
}

// ===========================================================================
// Kernel 1: q/k projection
// ===========================================================================
__global__ __launch_bounds__(256) void qk_kernel(
    const float* __restrict__ x1, const float* __restrict__ x2,
    const float* __restrict__ Wq, const float* __restrict__ bq,
    const float* __restrict__ Wk, const float* __restrict__ bk)
{
    __shared__ float xs[64][33];
    __shared__ float wqs[16][64];
    __shared__ float wks[16][64];

    const int n0  = blockIdx.x * 32;
    const int b   = blockIdx.y;
    const int tid = threadIdx.x;
    const int nl  = tid & 31;
    const int dg  = tid >> 5;

    float aq0 = 0.f, aq1 = 0.f, ak0 = 0.f, ak1 = 0.f;

    for (int c0 = 0; c0 < TWO_C; c0 += 64) {
        for (int r = dg; r < 64; r += 8) {
            const int c = c0 + r;
            const float* src = (c < CH) ? x1 : x2;
            xs[r][nl] = src[((size_t)b * CH + (c & (CH - 1))) * NPIX + n0 + nl];
        }
        for (int i = tid; i < 16 * 64; i += 256) {
            const int d = i >> 6, cc = i & 63;
            wqs[d][cc] = Wq[d * TWO_C + c0 + cc];
            wks[d][cc] = Wk[d * TWO_C + c0 + cc];
        }
        __syncthreads();
        #pragma unroll
        for (int cc = 0; cc < 64; cc++) {
            const float xv = xs[cc][nl];
            aq0 = fmaf(wqs[dg    ][cc], xv, aq0);
            aq1 = fmaf(wqs[dg + 8][cc], xv, aq1);
            ak0 = fmaf(wks[dg    ][cc], xv, ak0);
            ak1 = fmaf(wks[dg + 8][cc], xv, ak1);
        }
        __syncthreads();
    }

    const size_t base = (size_t)b * DQK * NPIX + n0 + nl;
    g_q[base + (size_t)(dg    ) * NPIX] = aq0 + bq[dg];
    g_q[base + (size_t)(dg + 8) * NPIX] = aq1 + bq[dg + 8];
    g_k[base + (size_t)(dg    ) * NPIX] = ak0 + bk[dg];
    g_k[base + (size_t)(dg + 8) * NPIX] = ak1 + bk[dg + 8];
}

// ===========================================================================
// Kernel 2: v projection GEMM (SIMT fp32; epilogue stores V as fp16)
// ===========================================================================
__global__ __launch_bounds__(256, 2) void v_gemm_kernel(
    const float* __restrict__ x1, const float* __restrict__ x2,
    const float* __restrict__ Wv1, const float* __restrict__ bv1,
    const float* __restrict__ Wv2, const float* __restrict__ bv2)
{
    __shared__ float As[2][TK][BM + PAD];
    __shared__ float Bs[2][TK][BN + PAD];

    const int which = blockIdx.z & 1;
    const int b     = blockIdx.z >> 1;
    const float* __restrict__ Wv = which ? Wv2 : Wv1;
    const float* __restrict__ bv = which ? bv2 : bv1;
    const float* __restrict__ Xb = (which ? x2 : x1) + (size_t)b * CH * NPIX;
    __half* __restrict__ V       = g_v_h[which] + (size_t)b * CH * NPIX;

    const int n0  = blockIdx.x * BN;
    const int o0  = blockIdx.y * BM;
    const int tid = threadIdx.x;
    const int tx  = tid & 15, ty = tid >> 4;

    const int ar  = tid >> 2;
    const int ak  = (tid & 3) << 2;
    const int bkr = tid >> 5;
    const int bj  = (tid & 31) << 2;

    float acc[8][8];
    #pragma unroll
    for (int r = 0; r < 8; r++)
        #pragma unroll
        for (int s = 0; s < 8; s++) acc[r][s] = 0.f;

    const int KT = CH / TK;
    float4 a0n, a1n, b0n, b1n;

    {
        const float* ap = Wv + (o0 + ar) * CH + ak;
        a0n = *(const float4*)ap;
        a1n = *(const float4*)(ap + 64 * CH);
        const float* bp = Xb + (size_t)bkr * NPIX + n0 + bj;
        b0n = *(const float4*)bp;
        b1n = *(const float4*)(bp + (size_t)8 * NPIX);
        As[0][ak + 0][ar] = a0n.x; As[0][ak + 1][ar] = a0n.y;
        As[0][ak + 2][ar] = a0n.z; As[0][ak + 3][ar] = a0n.w;
        As[0][ak + 0][ar + 64] = a1n.x; As[0][ak + 1][ar + 64] = a1n.y;
        As[0][ak + 2][ar + 64] = a1n.z; As[0][ak + 3][ar + 64] = a1n.w;
        *(float4*)&Bs[0][bkr    ][bj] = b0n;
        *(float4*)&Bs[0][bkr + 8][bj] = b1n;
    }
    __syncthreads();

    for (int kt = 0; kt < KT; kt++) {
        const int cur = kt & 1;
        const bool pf = (kt + 1 < KT);
        if (pf) {
            const int kc = (kt + 1) * TK;
            const float* ap = Wv + (o0 + ar) * CH + kc + ak;
            a0n = *(const float4*)ap;
            a1n = *(const float4*)(ap + 64 * CH);
            const float* bp = Xb + (size_t)(kc + bkr) * NPIX + n0 + bj;
            b0n = *(const float4*)bp;
            b1n = *(const float4*)(bp + (size_t)8 * NPIX);
        }
        #pragma unroll
        for (int k = 0; k < TK; k++) {
            const float4 a0 = *(const float4*)&As[cur][k][ty * 4];
            const float4 a1 = *(const float4*)&As[cur][k][64 + ty * 4];
            const float4 b0 = *(const float4*)&Bs[cur][k][tx * 4];
            const float4 b1 = *(const float4*)&Bs[cur][k][64 + tx * 4];
            const float av[8] = {a0.x, a0.y, a0.z, a0.w, a1.x, a1.y, a1.z, a1.w};
            const float bw[8] = {b0.x, b0.y, b0.z, b0.w, b1.x, b1.y, b1.z, b1.w};
            #pragma unroll
            for (int r = 0; r < 8; r++)
                #pragma unroll
                for (int s = 0; s < 8; s++)
                    acc[r][s] = fmaf(av[r], bw[s], acc[r][s]);
        }
        if (pf) {
            const int nb = cur ^ 1;
            As[nb][ak + 0][ar] = a0n.x; As[nb][ak + 1][ar] = a0n.y;
            As[nb][ak + 2][ar] = a0n.z; As[nb][ak + 3][ar] = a0n.w;
            As[nb][ak + 0][ar + 64] = a1n.x; As[nb][ak + 1][ar + 64] = a1n.y;
            As[nb][ak + 2][ar + 64] = a1n.z; As[nb][ak + 3][ar + 64] = a1n.w;
            *(float4*)&Bs[nb][bkr    ][bj] = b0n;
            *(float4*)&Bs[nb][bkr + 8][bj] = b1n;
        }
        __syncthreads();
    }

    #pragma unroll
    for (int rg = 0; rg < 2; rg++)
        #pragma unroll
        for (int rr = 0; rr < 4; rr++) {
            const int r = rg * 4 + rr;
            const int o = o0 + rg * 64 + ty * 4 + rr;
            const float bias = __ldg(&bv[o]);
            __half* dst = V + (size_t)o * NPIX + n0;
            uint2 h0, h1;
            h0.x = pack_h2(acc[r][0] + bias, acc[r][1] + bias);
            h0.y = pack_h2(acc[r][2] + bias, acc[r][3] + bias);
            h1.x = pack_h2(acc[r][4] + bias, acc[r][5] + bias);
            h1.y = pack_h2(acc[r][6] + bias, acc[r][7] + bias);
            *(uint2*)(dst + tx * 4)      = h0;
            *(uint2*)(dst + 64 + tx * 4) = h1;
        }
}

// ===========================================================================
// Kernel 3: energy + softmax -> fp32 attention (d_out) + fp16 copy (scratch)
// ===========================================================================
__global__ __launch_bounds__(256) void attn_kernel(float* __restrict__ att)
{
    __shared__ float ks[16][256];
    __shared__ float qs[16][32];
    __shared__ float s_mx[32];
    __shared__ float s_inv[32];

    const int n0   = blockIdx.x * 32;
    const int b    = blockIdx.y;
    const int tid  = threadIdx.x;
    const int lane = tid & 31;
    const int w    = tid >> 5;
    const int rb   = w * 4;

    const float* __restrict__ qb = g_q + (size_t)b * DQK * NPIX;
    const float* __restrict__ kb = g_k + (size_t)b * DQK * NPIX;
    float* __restrict__ attb     = att + (size_t)b * NPIX * NPIX;
    __half* __restrict__ atth    = g_att_h + (size_t)b * NPIX * NPIX;

    for (int i = tid; i < 512; i += 256) {
        const int d = i >> 5, nl = i & 31;
        qs[d][nl] = qb[(size_t)d * NPIX + n0 + nl];
    }
    __syncthreads();
    float qr[4][16];
    #pragma unroll
    for (int rr = 0; rr < 4; rr++)
        #pragma unroll
        for (int d = 0; d < 16; d++)
            qr[rr][d] = qs[d][rb + rr];

    float mx[4], sm[4];
    #pragma unroll
    for (int rr = 0; rr < 4; rr++) { mx[rr] = -1e30f; sm[rr] = 0.f; }

    for (int m0 = 0; m0 < NPIX; m0 += 256) {
        __syncthreads();
        #pragma unroll
        for (int r = 0; r < 4; r++) {
            const int lin = tid + 256 * r;
            const int d = lin >> 6, mm4 = (lin & 63) << 2;
            *(float4*)&ks[d][mm4] = *(const float4*)&kb[(size_t)d * NPIX + m0 + mm4];
        }
        __syncthreads();
        #pragma unroll
        for (int it = 0; it < 8; it++) {
            const int mm = lane + it * 32;
            float e0 = 0.f, e1 = 0.f, e2 = 0.f, e3 = 0.f;
            #pragma unroll
            for (int d = 0; d < 16; d++) {
                const float kv = ks[d][mm];
                e0 = fmaf(qr[0][d], kv, e0);
                e1 = fmaf(qr[1][d], kv, e1);
                e2 = fmaf(qr[2][d], kv, e2);
                e3 = fmaf(qr[3][d], kv, e3);
            }
            { const float dd = e0 - mx[0]; if (dd > 0.f) { sm[0] = sm[0] * __expf(-dd) + 1.f; mx[0] = e0; } else sm[0] += __expf(dd); }
            { const float dd = e1 - mx[1]; if (dd > 0.f) { sm[1] = sm[1] * __expf(-dd) + 1.f; mx[1] = e1; } else sm[1] += __expf(dd); }
            { const float dd = e2 - mx[2]; if (dd > 0.f) { sm[2] = sm[2] * __expf(-dd) + 1.f; mx[2] = e2; } else sm[2] += __expf(dd); }
            { const float dd = e3 - mx[3]; if (dd > 0.f) { sm[3] = sm[3] * __expf(-dd) + 1.f; mx[3] = e3; } else sm[3] += __expf(dd); }
        }
    }

    #pragma unroll
    for (int rr = 0; rr < 4; rr++) {
        float m = mx[rr], s = sm[rr];
        #pragma unroll
        for (int off = 16; off; off >>= 1) {
            const float om = __shfl_xor_sync(0xffffffffu, m, off);
            const float os = __shfl_xor_sync(0xffffffffu, s, off);
            const float nm = fmaxf(m, om);
            s = s * __expf(m - nm) + os * __expf(om - nm);
            m = nm;
        }
        if (lane == 0) { s_mx[rb + rr] = m; s_inv[rb + rr] = 1.f / s; }
    }
    __syncthreads();
    float fm[4], fi[4];
    #pragma unroll
    for (int rr = 0; rr < 4; rr++) { fm[rr] = s_mx[rb + rr]; fi[rr] = s_inv[rb + rr]; }

    for (int m0 = 0; m0 < NPIX; m0 += 256) {
        __syncthreads();
        #pragma unroll
        for (int r = 0; r < 4; r++) {
            const int lin = tid + 256 * r;
            const int d = lin >> 6, mm4 = (lin & 63) << 2;
            *(float4*)&ks[d][mm4] = *(const float4*)&kb[(size_t)d * NPIX + m0 + mm4];
        }
        __syncthreads();
        #pragma unroll
        for (int it = 0; it < 8; it++) {
            const int mm = lane + it * 32;
            float e0 = 0.f, e1 = 0.f, e2 = 0.f, e3 = 0.f;
            #pragma unroll
            for (int d = 0; d < 16; d++) {
                const float kv = ks[d][mm];
                e0 = fmaf(qr[0][d], kv, e0);
                e1 = fmaf(qr[1][d], kv, e1);
                e2 = fmaf(qr[2][d], kv, e2);
                e3 = fmaf(qr[3][d], kv, e3);
            }
            const float p0 = __expf(e0 - fm[0]) * fi[0];
            const float p1 = __expf(e1 - fm[1]) * fi[1];
            const float p2 = __expf(e2 - fm[2]) * fi[2];
            const float p3 = __expf(e3 - fm[3]) * fi[3];
            const size_t i0 = (size_t)(n0 + rb + 0) * NPIX + m0 + mm;
            const size_t i1 = (size_t)(n0 + rb + 1) * NPIX + m0 + mm;
            const size_t i2 = (size_t)(n0 + rb + 2) * NPIX + m0 + mm;
            const size_t i3 = (size_t)(n0 + rb + 3) * NPIX + m0 + mm;
            attb[i0] = p0; attb[i1] = p1; attb[i2] = p2; attb[i3] = p3;
            atth[i0] = __float2half_rn(p0); atth[i1] = __float2half_rn(p1);
            atth[i2] = __float2half_rn(p2); atth[i3] = __float2half_rn(p3);
        }
    }
}

// ===========================================================================
// Kernel 4: out-bmm via fp16 HMMA m16n8k16 + ldmatrix, 16 warps/CTA.
//   D[c, n] = sum_m Vh[c, m] * AttH[n, m]; out = D + x (fp32).
//   Block 128(c) x 256(n), BK=32 fp16, 4-stage cp.async ring.
//   16 warps (4 x 4), 32x64 warp tiles -> 4 warps/SMSP for latency hiding.
//   Smem rows = 64 B; 16B-chunk swizzle: j ^= (row>>1)&3.
// ===========================================================================
#define HBM_ 128
#define HBN_ 256
#define HBK_ 32
#define H_A_BYTES (HBM_ * 64)                    // 8192
#define H_STAGE   ((HBM_ + HBN_) * 64)           // 24576
#define HNSTAGE   4
#define HSMEM     (HNSTAGE * H_STAGE)            // 98304

__global__ __launch_bounds__(512, 1) void out_gemm_h(
    const float* __restrict__ x1, const float* __restrict__ x2,
    float* __restrict__ out)
{
    extern __shared__ char smraw[];
    const uint32_t smb = smem_u32(smraw);

    const int tid  = threadIdx.x;
    const int wid  = tid >> 5;     // 0..15
    const int lane = tid & 31;
    const int grp  = lane >> 2;
    const int tig  = lane & 3;
    const int wm   = wid >> 2;     // 0..3 -> m offset 32*wm
    const int wn   = wid & 3;      // 0..3 -> n offset 64*wn

    const int which = blockIdx.z & 1;
    const int b     = blockIdx.z >> 1;
    const int n0    = blockIdx.x * HBN_;
    const int c0    = blockIdx.y * HBM_;

    const __half* __restrict__ Vb = g_v_h[which] + (size_t)b * CH * NPIX;
    const __half* __restrict__ Ah = g_att_h + (size_t)b * NPIX * NPIX;

    // ---- producer mapping (swizzled 16B chunks), 512 threads ----
    // A: 128 rows x 4 chunks = 512 -> 1 per thread
    const int a_row = tid >> 2;
    const int a_j   = tid & 3;
    const uint32_t aDst = smb + (uint32_t)(a_row * 64 + ((a_j ^ ((a_row >> 1) & 3)) * 16));
    const __half* aSrc = Vb + (size_t)(c0 + a_row) * NPIX + a_j * 8;
    // B: 256 rows x 4 chunks = 1024 -> 2 per thread
    const int b_row = tid >> 1;
    const int b_j0  = (tid & 1) * 2;
    const int b_sw  = (b_row >> 1) & 3;
    uint32_t bDst[2];
    #pragma unroll
    for (int i = 0; i < 2; i++)
        bDst[i] = smb + (uint32_t)(H_A_BYTES + b_row * 64 + (((b_j0 + i) ^ b_sw) * 16));
    const __half* bSrc = Ah + (size_t)(n0 + b_row) * NPIX + b_j0 * 8;

    // ---- ldmatrix lane constants ----
    const int radd = lane & 15;
    const int jA   = lane >> 4;
    const int lsw  = (radd >> 1) & 3;
    const uint32_t rowOff = (uint32_t)radd * 64;
    uint32_t cswk[2];
    cswk[0] = (uint32_t)(((0 + jA) ^ lsw) * 16);
    cswk[1] = (uint32_t)(((2 + jA) ^ lsw) * 16);

    float acc[2][8][4];
    #pragma unroll
    for (int mt = 0; mt < 2; mt++)
        #pragma unroll
        for (int nt = 0; nt < 8; nt++)
            #pragma unroll
            for (int q = 0; q < 4; q++) acc[mt][nt][q] = 0.f;

    const int KT = NPIX / HBK_;   // 128

    // prologue: stages 0..2
    #pragma unroll
    for (int s = 0; s < HNSTAGE - 1; s++) {
        const uint32_t so = (uint32_t)(s * H_STAGE);
        const int kc = s * HBK_;
        CP_ASYNC16(aDst + so, aSrc + kc);
        #pragma unroll
        for (int i = 0; i < 2; i++) CP_ASYNC16(bDst[i] + so, bSrc + kc + i * 8);
        CP_COMMIT();
    }

    const uint32_t aWarp = smb + (uint32_t)(wm * 32) * 64 + rowOff;
    const uint32_t bWarp = smb + H_A_BYTES + (uint32_t)(wn * 64) * 64 + rowOff;

    for (int kt = 0; kt < KT; kt++) {
        CP_WAIT2();
        __syncthreads();

        const int nk = kt + HNSTAGE - 1;
        if (nk < KT) {
            const uint32_t so = (uint32_t)((nk & (HNSTAGE - 1)) * H_STAGE);
            const int kc = nk * HBK_;
            CP_ASYNC16(aDst + so, aSrc + kc);
            #pragma unroll
            for (int i = 0; i < 2; i++) CP_ASYNC16(bDst[i] + so, bSrc + kc + i * 8);
        }
        CP_COMMIT();

        const uint32_t so = (uint32_t)((kt & (HNSTAGE - 1)) * H_STAGE);
        const uint32_t aB = aWarp + so;
        const uint32_t bB = bWarp + so;

        #pragma unroll
        for (int ksp = 0; ksp < 2; ksp++) {
            uint32_t af[2][4];
            #pragma unroll
            for (int mt = 0; mt < 2; mt++)
                LDSM_X4(af[mt][0], af[mt][1], af[mt][2], af[mt][3],
                        aB + (uint32_t)(mt * 1024) + cswk[ksp]);
            uint32_t bf[8][2];
            #pragma unroll
            for (int ntp = 0; ntp < 4; ntp++) {
                uint32_t q0, q1, q2, q3;
                LDSM_X4(q0, q1, q2, q3, bB + (uint32_t)(ntp * 1024) + cswk[ksp]);
                bf[2 * ntp    ][0] = q0; bf[2 * ntp    ][1] = q2;
                bf[2 * ntp + 1][0] = q1; bf[2 * ntp + 1][1] = q3;
            }
            #pragma unroll
            for (int mt = 0; mt < 2; mt++)
                #pragma unroll
                for (int nt = 0; nt < 8; nt++)
                    mma_f16(acc[mt][nt], af[mt], bf[nt]);
        }
        __syncthreads();
    }
    CP_WAIT0();

    // ---- epilogue: + residual x (fp32), store ----
    const float* __restrict__ Xb = (which ? x2 : x1) + (size_t)b * CH * NPIX;
    float* __restrict__ Ob = out + (size_t)which * BATCH * CH * NPIX + (size_t)b * CH * NPIX;

    #pragma unroll
    for (int mt = 0; mt < 2; mt++) {
        const int row0 = c0 + wm * 32 + mt * 16 + grp;
        const size_t r0b = (size_t)row0 * NPIX;
        const size_t r1b = (size_t)(row0 + 8) * NPIX;
        #pragma unroll
        for (int nt = 0; nt < 8; nt++) {
            const int col = n0 + wn * 64 + nt * 8 + tig * 2;
            const float2 x0 = *(const float2*)&Xb[r0b + col];
            const float2 x1v = *(const float2*)&Xb[r1b + col];
            float2 o0, o1;
            o0.x = acc[mt][nt][0] + x0.x;  o0.y = acc[mt][nt][1] + x0.y;
            o1.x = acc[mt][nt][2] + x1v.x; o1.y = acc[mt][nt][3] + x1v.y;
            *(float2*)&Ob[r0b + col] = o0;
            *(float2*)&Ob[r1b + col] = o1;
        }
    }
}

// ===========================================================================
// launch
// ===========================================================================
extern "C" void kernel_launch(void* const* d_in, const int* in_sizes, int n_in,
                              void* d_out, int out_size)
{
    (void)in_sizes; (void)n_in; (void)out_size;
    const float* x1  = (const float*)d_in[0];
    const float* x2  = (const float*)d_in[1];
    const float* Wq  = (const float*)d_in[2];
    const float* bq  = (const float*)d_in[3];
    const float* Wk  = (const float*)d_in[4];
    const float* bk  = (const float*)d_in[5];
    const float* Wv1 = (const float*)d_in[6];
    const float* bv1 = (const float*)d_in[7];
    const float* Wv2 = (const float*)d_in[8];
    const float* bv2 = (const float*)d_in[9];

    float* out = (float*)d_out;
    float* att = out + (size_t)2 * BATCH * CH * NPIX;

    cudaFuncSetAttribute(out_gemm_h, cudaFuncAttributeMaxDynamicSharedMemorySize, HSMEM);

    qk_kernel<<<dim3(NPIX / 32, BATCH), 256>>>(x1, x2, Wq, bq, Wk, bk);
    v_gemm_kernel<<<dim3(NPIX / BN, CH / BM, BATCH * 2), 256>>>(x1, x2, Wv1, bv1, Wv2, bv2);
    attn_kernel<<<dim3(NPIX / 32, BATCH), 256>>>(att);
    out_gemm_h<<<dim3(NPIX / HBN_, CH / HBM_, BATCH * 2), 512, HSMEM>>>(x1, x2, out);
}